// round 1
// baseline (speedup 1.0000x reference)
#include <cuda_runtime.h>
#include <cstdint>

// ---- static problem config ----
#define HMAP      524288u          // 2^19 entries per level
#define HMASK     (HMAP - 1u)
#define NLEVEL    3
#define NPTS      2097152          // B
#define TBL_ELEMS (NLEVEL * HMAP)  // 1,572,864
#define PRIME1    2654435761u
#define PRIME2    805459861u

// Packed interleaved table: tbl[level*HMAP + m] = (c0, c1)
__device__ float2 g_tbl[TBL_ELEMS];

// ---------------------------------------------------------------------------
// Pass 1: pack triplane [3,2,1024,512] -> interleaved float2 table.
// plane p, entry m: c0 at p*1048576 + m, c1 at p*1048576 + 524288 + m.
// ---------------------------------------------------------------------------
__global__ __launch_bounds__(256) void pack_kernel(const float* __restrict__ tri) {
    unsigned n = blockIdx.x * 256u + threadIdx.x;
    if (n >= TBL_ELEMS) return;
    unsigned p = n >> 19;            // n / HMAP
    unsigned m = n & HMASK;
    const float* base = tri + (size_t)p * (2u * HMAP);
    g_tbl[n] = make_float2(base[m], base[m + HMAP]);
}

// ---------------------------------------------------------------------------
// Pass 2: encode. One thread per query point.
// ---------------------------------------------------------------------------
__global__ __launch_bounds__(256) void enc_kernel(const float* __restrict__ xin,
                                                  float2* __restrict__ out) {
    unsigned i = blockIdx.x * 256u + threadIdx.x;
    if (i >= NPTS) return;

    const float x = xin[3u * i + 0u];
    const float y = xin[3u * i + 1u];
    const float z = xin[3u * i + 2u];
    // map [-1,1] -> [0,1]
    const float x0 = (x + 1.0f) * 0.5f;
    const float y0 = (y + 1.0f) * 0.5f;
    const float z0 = (z + 1.0f) * 0.5f;

    float accx = 0.0f, accy = 0.0f;

#pragma unroll
    for (int lv = 0; lv < NLEVEL; lv++) {
        const float scale = (float)((128 << lv) - 1);   // 127, 255, 511 (exact)

        const float px = x0 * scale + 0.5f;
        const float py = y0 * scale + 0.5f;
        const float pz = z0 * scale + 0.5f;
        const float gx = floorf(px), gy = floorf(py), gz = floorf(pz);
        const float rx = px - gx, ry = py - gy, rz = pz - gz;

        const unsigned ix = (unsigned)gx;
        const unsigned iy = (unsigned)gy;
        const unsigned iz = (unsigned)gz;

        // hash components (uint32 wrap, as in CUDA/instant-NGP)
        const unsigned hx0 = ix;
        const unsigned hx1 = ix + 1u;
        const unsigned hy0 = iy * PRIME1;
        const unsigned hy1 = (iy + 1u) * PRIME1;
        const unsigned hz0 = iz * PRIME2;
        const unsigned hz1 = (iz + 1u) * PRIME2;

        const float2* __restrict__ tbl = g_tbl + (unsigned)lv * HMAP;

        // compute all 8 indices first -> maximize outstanding loads (MLP)
        const unsigned i000 = (hx0 ^ hy0 ^ hz0) & HMASK;
        const unsigned i100 = (hx1 ^ hy0 ^ hz0) & HMASK;
        const unsigned i010 = (hx0 ^ hy1 ^ hz0) & HMASK;
        const unsigned i110 = (hx1 ^ hy1 ^ hz0) & HMASK;
        const unsigned i001 = (hx0 ^ hy0 ^ hz1) & HMASK;
        const unsigned i101 = (hx1 ^ hy0 ^ hz1) & HMASK;
        const unsigned i011 = (hx0 ^ hy1 ^ hz1) & HMASK;
        const unsigned i111 = (hx1 ^ hy1 ^ hz1) & HMASK;

        const float2 f000 = __ldg(&tbl[i000]);
        const float2 f100 = __ldg(&tbl[i100]);
        const float2 f010 = __ldg(&tbl[i010]);
        const float2 f110 = __ldg(&tbl[i110]);
        const float2 f001 = __ldg(&tbl[i001]);
        const float2 f101 = __ldg(&tbl[i101]);
        const float2 f011 = __ldg(&tbl[i011]);
        const float2 f111 = __ldg(&tbl[i111]);

        const float wx0 = 1.0f - rx, wx1 = rx;
        const float wy0 = 1.0f - ry, wy1 = ry;
        const float wz0 = 1.0f - rz, wz1 = rz;

        const float w000 = wx0 * wy0 * wz0;
        const float w100 = wx1 * wy0 * wz0;
        const float w010 = wx0 * wy1 * wz0;
        const float w110 = wx1 * wy1 * wz0;
        const float w001 = wx0 * wy0 * wz1;
        const float w101 = wx1 * wy0 * wz1;
        const float w011 = wx0 * wy1 * wz1;
        const float w111 = wx1 * wy1 * wz1;

        accx += w000 * f000.x + w100 * f100.x + w010 * f010.x + w110 * f110.x
              + w001 * f001.x + w101 * f101.x + w011 * f011.x + w111 * f111.x;
        accy += w000 * f000.y + w100 * f100.y + w010 * f010.y + w110 * f110.y
              + w001 * f001.y + w101 * f101.y + w011 * f011.y + w111 * f111.y;
    }

    out[i] = make_float2(accx, accy);
}

extern "C" void kernel_launch(void* const* d_in, const int* in_sizes, int n_in,
                              void* d_out, int out_size) {
    // identify inputs by element count (triplane: 3*2*1024*512 = 3,145,728;
    // inputs: 2,097,152*3 = 6,291,456)
    const float* tri = (const float*)d_in[0];
    const float* xin = (const float*)d_in[1];
    if (in_sizes[0] != 3145728) {
        tri = (const float*)d_in[1];
        xin = (const float*)d_in[0];
    }
    float2* out = (float2*)d_out;

    pack_kernel<<<(TBL_ELEMS + 255) / 256, 256>>>(tri);
    enc_kernel<<<(NPTS + 255) / 256, 256>>>(xin, out);
}

// round 2
// speedup vs baseline: 1.7828x; 1.7828x over previous
#include <cuda_runtime.h>
#include <cstdint>

// ---- static problem config ----
#define HMAP      524288u          // 2^19 entries per level
#define HMASK     (HMAP - 1u)
#define NLEVEL    3
#define NPTS      2097152          // B
#define TBL_ELEMS (NLEVEL * HMAP)  // 1,572,864
#define PRIME1    2654435761u
#define PRIME2    805459861u

// Packed interleaved table: tbl[level*HMAP + m] = (c0, c1).
// 16B-aligned so aligned float4 covers entry pairs {2j, 2j+1}.
__device__ __align__(16) float2 g_tbl[TBL_ELEMS];

// ---------------------------------------------------------------------------
// Pass 1: pack triplane [3,2,1024,512] -> interleaved float2 table.
// ---------------------------------------------------------------------------
__global__ __launch_bounds__(256) void pack_kernel(const float* __restrict__ tri) {
    unsigned n = blockIdx.x * 256u + threadIdx.x;
    if (n >= TBL_ELEMS) return;
    unsigned p = n >> 19;            // n / HMAP
    unsigned m = n & HMASK;
    const float* base = tri + (size_t)p * (2u * HMAP);
    g_tbl[n] = make_float2(base[m], base[m + HMAP]);
}

// ---------------------------------------------------------------------------
// Pass 2: encode. One thread per query point.
// x-pair sector fusion: when ix is even, corner indices (ix^r) and
// ((ix+1)^r) differ only in bit 0 -> one aligned float4 load covers both.
// ---------------------------------------------------------------------------
__global__ __launch_bounds__(256) void enc_kernel(const float* __restrict__ xin,
                                                  float2* __restrict__ out) {
    unsigned i = blockIdx.x * 256u + threadIdx.x;
    if (i >= NPTS) return;

    const float x = xin[3u * i + 0u];
    const float y = xin[3u * i + 1u];
    const float z = xin[3u * i + 2u];
    const float x0 = (x + 1.0f) * 0.5f;
    const float y0 = (y + 1.0f) * 0.5f;
    const float z0 = (z + 1.0f) * 0.5f;

    float accx = 0.0f, accy = 0.0f;

#pragma unroll
    for (int lv = 0; lv < NLEVEL; lv++) {
        const float scale = (float)((128 << lv) - 1);   // 127, 255, 511

        const float px = x0 * scale + 0.5f;
        const float py = y0 * scale + 0.5f;
        const float pz = z0 * scale + 0.5f;
        const float gx = floorf(px), gy = floorf(py), gz = floorf(pz);
        const float rx = px - gx, ry = py - gy, rz = pz - gz;

        const unsigned ix = (unsigned)gx;
        const unsigned iy = (unsigned)gy;
        const unsigned iz = (unsigned)gz;

        const unsigned hy0 = iy * PRIME1;
        const unsigned hy1 = hy0 + PRIME1;       // (iy+1)*PRIME1 mod 2^32
        const unsigned hz0 = iz * PRIME2;
        const unsigned hz1 = hz0 + PRIME2;

        unsigned r[4];
        r[0] = hy0 ^ hz0;   // (y0,z0)
        r[1] = hy1 ^ hz0;   // (y1,z0)
        r[2] = hy0 ^ hz1;   // (y0,z1)
        r[3] = hy1 ^ hz1;   // (y1,z1)

        float2 fa[4], fb[4];   // fa = x-corner ix, fb = x-corner ix+1

        if ((ix & 1u) == 0u) {
            // even: each x-pair lives in one aligned float4 (one 32B sector)
            const float4* __restrict__ t4 =
                reinterpret_cast<const float4*>(g_tbl + (unsigned)lv * HMAP);
#pragma unroll
            for (int c = 0; c < 4; c++) {
                const unsigned m = (ix ^ r[c]) & HMASK;
                const float4 q = __ldg(&t4[m >> 1]);
                if (m & 1u) {
                    fa[c] = make_float2(q.z, q.w);
                    fb[c] = make_float2(q.x, q.y);
                } else {
                    fa[c] = make_float2(q.x, q.y);
                    fb[c] = make_float2(q.z, q.w);
                }
            }
        } else {
            const float2* __restrict__ t2 = g_tbl + (unsigned)lv * HMAP;
            const unsigned ix1 = ix + 1u;
#pragma unroll
            for (int c = 0; c < 4; c++) {
                fa[c] = __ldg(&t2[(ix  ^ r[c]) & HMASK]);
                fb[c] = __ldg(&t2[(ix1 ^ r[c]) & HMASK]);
            }
        }

        const float wx0 = 1.0f - rx, wx1 = rx;
        const float wy0 = 1.0f - ry, wy1 = ry;
        const float wz0 = 1.0f - rz, wz1 = rz;

        float wyz[4];
        wyz[0] = wy0 * wz0;
        wyz[1] = wy1 * wz0;
        wyz[2] = wy0 * wz1;
        wyz[3] = wy1 * wz1;

#pragma unroll
        for (int c = 0; c < 4; c++) {
            accx += wyz[c] * (wx0 * fa[c].x + wx1 * fb[c].x);
            accy += wyz[c] * (wx0 * fa[c].y + wx1 * fb[c].y);
        }
    }

    out[i] = make_float2(accx, accy);
}

extern "C" void kernel_launch(void* const* d_in, const int* in_sizes, int n_in,
                              void* d_out, int out_size) {
    const float* tri = (const float*)d_in[0];
    const float* xin = (const float*)d_in[1];
    if (in_sizes[0] != 3145728) {
        tri = (const float*)d_in[1];
        xin = (const float*)d_in[0];
    }
    float2* out = (float2*)d_out;

    pack_kernel<<<(TBL_ELEMS + 255) / 256, 256>>>(tri);
    enc_kernel<<<(NPTS + 255) / 256, 256>>>(xin, out);
}

// round 3
// speedup vs baseline: 1.9539x; 1.0960x over previous
#include <cuda_runtime.h>
#include <cstdint>

// ---- static problem config ----
#define HMAP      524288u          // 2^19 entries per level
#define HMASK     (HMAP - 1u)
#define NLEVEL    3
#define NPTS      2097152u         // B
#define TBL_ELEMS (NLEVEL * HMAP)  // 1,572,864
#define NPAIRS    (TBL_ELEMS / 2)  // 786,432
#define PRIME1    2654435761u
#define PRIME2    805459861u

// Pair-packed tables. Tk packs entry pairs {m, m^k} into one aligned float4:
//   Tk[((m & ~k)>>1) + t],  t = min(low, k-low), low = m & k
//   slot 0 = member with low <= k/2, slot 1 = the other.
// T1 doubles as the flat float2 table for the scalar fallback.
__device__ __align__(16) float4 g_t1 [NPAIRS];
__device__ __align__(16) float4 g_t3 [NPAIRS];
__device__ __align__(16) float4 g_t7 [NPAIRS];
__device__ __align__(16) float4 g_t15[NPAIRS];

// entry m of the flat multi-level table, read from raw triplane layout
__device__ __forceinline__ float2 ent(const float* __restrict__ tri, unsigned m) {
    unsigned p  = m >> 19;
    unsigned mm = m & HMASK;
    const float* base = tri + (size_t)p * (2u * HMAP);
    return make_float2(base[mm], base[mm + HMAP]);
}

__device__ __forceinline__ float4 pack2(float2 lo, float2 hi) {
    return make_float4(lo.x, lo.y, hi.x, hi.y);
}

// ---------------------------------------------------------------------------
// Pass 1: build all four pair-packed tables from the raw triplane.
// ---------------------------------------------------------------------------
__global__ __launch_bounds__(256) void pack_kernel(const float* __restrict__ tri) {
    unsigned j = blockIdx.x * 256u + threadIdx.x;
    if (j >= NPAIRS) return;

    // T1: pairs {2j, 2j+1}
    g_t1[j] = pack2(ent(tri, 2u * j), ent(tri, 2u * j + 1u));

    // T3: group of 4, pairs {b+a, b+3-a}, a = j&1
    {
        unsigned b = (j >> 1) << 2, a = j & 1u;
        g_t3[j] = pack2(ent(tri, b + a), ent(tri, b + 3u - a));
    }
    // T7: group of 8, pairs {b+t, b+7-t}, t = j&3
    {
        unsigned b = (j >> 2) << 3, t = j & 3u;
        g_t7[j] = pack2(ent(tri, b + t), ent(tri, b + 7u - t));
    }
    // T15: group of 16, pairs {b+t, b+15-t}, t = j&7
    {
        unsigned b = (j >> 3) << 4, t = j & 7u;
        g_t15[j] = pack2(ent(tri, b + t), ent(tri, b + 15u - t));
    }
}

// ---------------------------------------------------------------------------
// Pass 2: encode. One thread per query point.
// ---------------------------------------------------------------------------
__global__ __launch_bounds__(256) void enc_kernel(const float* __restrict__ xin,
                                                  float2* __restrict__ out) {
    unsigned i = blockIdx.x * 256u + threadIdx.x;
    if (i >= NPTS) return;

    const float x0 = (xin[3u * i + 0u] + 1.0f) * 0.5f;
    const float y0 = (xin[3u * i + 1u] + 1.0f) * 0.5f;
    const float z0 = (xin[3u * i + 2u] + 1.0f) * 0.5f;

    float accx = 0.0f, accy = 0.0f;

#pragma unroll
    for (int lv = 0; lv < NLEVEL; lv++) {
        const float scale = (float)((128 << lv) - 1);   // 127, 255, 511

        const float px = x0 * scale + 0.5f;
        const float py = y0 * scale + 0.5f;
        const float pz = z0 * scale + 0.5f;
        const float gx = floorf(px), gy = floorf(py), gz = floorf(pz);
        const float rx = px - gx, ry = py - gy, rz = pz - gz;

        const unsigned ix = (unsigned)gx;
        const unsigned iy = (unsigned)gy;
        const unsigned iz = (unsigned)gz;

        const unsigned hy0 = iy * PRIME1;
        const unsigned hy1 = hy0 + PRIME1;
        const unsigned hz0 = iz * PRIME2;
        const unsigned hz1 = hz0 + PRIME2;

        unsigned r[4];
        r[0] = hy0 ^ hz0;
        r[1] = hy1 ^ hz0;
        r[2] = hy0 ^ hz1;
        r[3] = hy1 ^ hz1;

        const unsigned lvoff = (unsigned)lv * (HMAP / 2u);  // in float4 pairs
        const unsigned tz = ix ^ (ix + 1u);                  // 2^(k+1)-1

        float2 fa[4], fb[4];   // fa = x-corner ix, fb = x-corner ix+1

        if (tz <= 15u) {
            const float4* __restrict__ tp =
                (tz == 1u) ? g_t1 : (tz == 3u) ? g_t3 : (tz == 7u) ? g_t7 : g_t15;
            const unsigned half = tz >> 1;
#pragma unroll
            for (int c = 0; c < 4; c++) {
                const unsigned m   = (ix ^ r[c]) & HMASK;
                const unsigned low = m & tz;
                const bool     hib = low > half;
                const unsigned t   = hib ? (tz - low) : low;
                const unsigned idx = ((m & ~tz) >> 1) + t + lvoff;
                const float4 q = __ldg(&tp[idx]);
                const float2 qlo = make_float2(q.x, q.y);
                const float2 qhi = make_float2(q.z, q.w);
                fa[c] = hib ? qhi : qlo;
                fb[c] = hib ? qlo : qhi;
            }
        } else {
            // rare: ix with >=4 trailing ones -> 8 scalar gathers from flat table
            const float2* __restrict__ t2 =
                reinterpret_cast<const float2*>(g_t1) + (unsigned)lv * HMAP;
            const unsigned ix1 = ix + 1u;
#pragma unroll
            for (int c = 0; c < 4; c++) {
                fa[c] = __ldg(&t2[(ix  ^ r[c]) & HMASK]);
                fb[c] = __ldg(&t2[(ix1 ^ r[c]) & HMASK]);
            }
        }

        const float wx0 = 1.0f - rx, wx1 = rx;
        const float wy0 = 1.0f - ry, wy1 = ry;
        const float wz0 = 1.0f - rz, wz1 = rz;

        float wyz[4];
        wyz[0] = wy0 * wz0;
        wyz[1] = wy1 * wz0;
        wyz[2] = wy0 * wz1;
        wyz[3] = wy1 * wz1;

#pragma unroll
        for (int c = 0; c < 4; c++) {
            accx += wyz[c] * (wx0 * fa[c].x + wx1 * fb[c].x);
            accy += wyz[c] * (wx0 * fa[c].y + wx1 * fb[c].y);
        }
    }

    out[i] = make_float2(accx, accy);
}

extern "C" void kernel_launch(void* const* d_in, const int* in_sizes, int n_in,
                              void* d_out, int out_size) {
    const float* tri = (const float*)d_in[0];
    const float* xin = (const float*)d_in[1];
    if (in_sizes[0] != 3145728) {
        tri = (const float*)d_in[1];
        xin = (const float*)d_in[0];
    }
    float2* out = (float2*)d_out;

    pack_kernel<<<(NPAIRS + 255) / 256, 256>>>(tri);
    enc_kernel<<<(NPTS + 255) / 256, 256>>>(xin, out);
}